// round 2
// baseline (speedup 1.0000x reference)
#include <cuda_runtime.h>
#include <math.h>

#define N_USER   100000
#define N_ITEM   50000
#define N_NODES_ (N_USER + N_ITEM)   // 150000
#define NNZ_     4800000
#define EMB      64
#define N_LAYERS 3
#define BATCH_   16384
#define EPS_     1e-12f
#define NEG_SLOPE 0.2f
#define TPAD     132                  // padded row stride for transposed tiles

// ---------------- scratch (device globals: allocation-free rule) -------------
__device__ float g_ego [N_NODES_ * EMB];        // current layer input (unnormalized)
__device__ float g_side[N_NODES_ * EMB];        // A_hat @ ego accumulator
__device__ float g_all [N_NODES_ * 4 * EMB];    // concat of 4 embedding blocks

// ------- init: ego = concat(user_emb, item_emb); all[:,0:64] = ego; side = 0 --
__global__ void init_kernel(const float* __restrict__ ue, const float* __restrict__ ie) {
    int idx = blockIdx.x * blockDim.x + threadIdx.x;      // float4 index
    const int total = N_NODES_ * EMB / 4;
    if (idx >= total) return;
    int node = idx >> 4;
    int c4   = idx & 15;
    float4 v;
    if (node < N_USER) v = __ldg((const float4*)ue + node * 16 + c4);
    else               v = __ldg((const float4*)ie + (node - N_USER) * 16 + c4);
    ((float4*)g_ego)[idx] = v;
    ((float4*)g_all)[node * 64 + c4] = v;
    ((float4*)g_side)[idx] = make_float4(0.f, 0.f, 0.f, 0.f);
}

// ---------------- SpMM: side[r] += val * ego[c], 16 threads per edge ----------
// NNZ*16 is an exact multiple of 256 -> every warp is full, shuffles are safe.
__global__ void spmm_kernel(const int* __restrict__ rows,
                            const int* __restrict__ cols,
                            const float* __restrict__ vals) {
    int t = blockIdx.x * blockDim.x + threadIdx.x;
    int e = t >> 4;
    int lane = threadIdx.x & 31;
    int l = lane & 15;
    int leader = lane & 16;           // 0 or 16: source lane for this half-warp
    int r = 0, c = 0; float v = 0.f;
    if (l == 0) {                     // lanes 0 and 16 load their edge's metadata
        r = __ldg(&rows[e]);
        c = __ldg(&cols[e]);
        v = __ldg(&vals[e]);
    }
    const unsigned m = 0xffffffffu;
    r = __shfl_sync(m, r, leader);
    c = __shfl_sync(m, c, leader);
    v = __shfl_sync(m, v, leader);
    float4 g = __ldg((const float4*)g_ego + c * 16 + l);
    float4 msg = make_float4(g.x * v, g.y * v, g.z * v, g.w * v);
    float* dst = g_side + ((size_t)r * EMB + l * 4);
    asm volatile("red.global.add.v4.f32 [%0], {%1,%2,%3,%4};"
                 :: "l"(dst), "f"(msg.x), "f"(msg.y), "f"(msg.z), "f"(msg.w) : "memory");
}

// ---------------- fused dense transform + leaky_relu + L2-normalize ----------
// 128-row tile, 256 threads, thread(tx,ty) computes rows ty*8..+7, cols tx*4..+3.
// S and P=ego*side staged TRANSPOSED in shared -> row operands load as LDS.128.
// Also zeroes g_side rows it consumed (ready for next layer's scatter).
__global__ void transform_kernel(const float* __restrict__ Wgc,
                                 const float* __restrict__ bgc,
                                 const float* __restrict__ Wbi,
                                 const float* __restrict__ bbi,
                                 int layer) {
    extern __shared__ float sh[];
    float* ST = sh;                        // [64][TPAD] transposed side
    float* PT = ST + 64 * TPAD;            // [64][TPAD] transposed ego*side
    float* Wg = PT + 64 * TPAD;            // [64][64]
    float* Wb = Wg + 64 * 64;              // [64][64]
    float* bs = Wb + 64 * 64;              // [64]

    const int tid = threadIdx.x;
    const int rowBase = blockIdx.x * 128;

    // stage weights (1024 float4 each)
    for (int i = tid; i < 1024; i += 256) {
        ((float4*)Wg)[i] = __ldg((const float4*)Wgc + i);
        ((float4*)Wb)[i] = __ldg((const float4*)Wbi + i);
    }
    if (tid < 64) bs[tid] = __ldg(bgc + tid) + __ldg(bbi + tid);

    // stage tiles transposed; consecutive lanes -> consecutive rows (conflict-free STS,
    // global reads stride 64B but every sector is consumed by sibling warps)
#pragma unroll
    for (int it = 0; it < 8; it++) {
        int i  = tid + 256 * it;
        int r  = i & 127;
        int c4 = i >> 7;
        int gr = rowBase + r;
        float4 s = make_float4(0.f, 0.f, 0.f, 0.f);
        float4 e = make_float4(0.f, 0.f, 0.f, 0.f);
        if (gr < N_NODES_) {
            s = ((const float4*)g_side)[gr * 16 + c4];
            e = ((const float4*)g_ego )[gr * 16 + c4];
            ((float4*)g_side)[gr * 16 + c4] = make_float4(0.f, 0.f, 0.f, 0.f); // fused zero
        }
        int k0 = c4 * 4;
        ST[(k0 + 0) * TPAD + r] = s.x;
        ST[(k0 + 1) * TPAD + r] = s.y;
        ST[(k0 + 2) * TPAD + r] = s.z;
        ST[(k0 + 3) * TPAD + r] = s.w;
        PT[(k0 + 0) * TPAD + r] = e.x * s.x;
        PT[(k0 + 1) * TPAD + r] = e.y * s.y;
        PT[(k0 + 2) * TPAD + r] = e.z * s.z;
        PT[(k0 + 3) * TPAD + r] = e.w * s.w;
    }
    __syncthreads();

    const int tx = tid & 15;
    const int ty = tid >> 4;
    float acc[8][4];
#pragma unroll
    for (int i = 0; i < 8; i++)
#pragma unroll
        for (int j = 0; j < 4; j++) acc[i][j] = 0.f;

#pragma unroll 4
    for (int k = 0; k < 64; k++) {
        float4 wg = *(const float4*)&Wg[k * 64 + tx * 4];
        float4 wb = *(const float4*)&Wb[k * 64 + tx * 4];
        float4 sA = *(const float4*)&ST[k * TPAD + ty * 8];
        float4 sB = *(const float4*)&ST[k * TPAD + ty * 8 + 4];
        float4 pA = *(const float4*)&PT[k * TPAD + ty * 8];
        float4 pB = *(const float4*)&PT[k * TPAD + ty * 8 + 4];
        float s[8] = {sA.x, sA.y, sA.z, sA.w, sB.x, sB.y, sB.z, sB.w};
        float p[8] = {pA.x, pA.y, pA.z, pA.w, pB.x, pB.y, pB.z, pB.w};
#pragma unroll
        for (int i = 0; i < 8; i++) {
            acc[i][0] += s[i] * wg.x + p[i] * wb.x;
            acc[i][1] += s[i] * wg.y + p[i] * wb.y;
            acc[i][2] += s[i] * wg.z + p[i] * wb.z;
            acc[i][3] += s[i] * wg.w + p[i] * wb.w;
        }
    }

    // epilogue: bias + leaky, row-norm across the 16 tx lanes (in-warp: lanes 0-15/16-31)
    const int colBase = tx * 4;
    float b0 = bs[colBase + 0], b1 = bs[colBase + 1];
    float b2 = bs[colBase + 2], b3 = bs[colBase + 3];
#pragma unroll
    for (int i = 0; i < 8; i++) {
        float x0 = acc[i][0] + b0;
        float x1 = acc[i][1] + b1;
        float x2 = acc[i][2] + b2;
        float x3 = acc[i][3] + b3;
        x0 = fmaxf(x0, NEG_SLOPE * x0);
        x1 = fmaxf(x1, NEG_SLOPE * x1);
        x2 = fmaxf(x2, NEG_SLOPE * x2);
        x3 = fmaxf(x3, NEG_SLOPE * x3);
        float sq = x0 * x0 + x1 * x1 + x2 * x2 + x3 * x3;
#pragma unroll
        for (int off = 1; off < 16; off <<= 1)
            sq += __shfl_xor_sync(0xffffffffu, sq, off);
        int gr = rowBase + ty * 8 + i;
        if (gr < N_NODES_) {
            float inv = 1.0f / fmaxf(sqrtf(sq), EPS_);
            *(float4*)&g_ego[(size_t)gr * EMB + colBase] =
                make_float4(x0, x1, x2, x3);
            *(float4*)&g_all[(size_t)gr * 256 + (layer + 1) * 64 + colBase] =
                make_float4(x0 * inv, x1 * inv, x2 * inv, x3 * inv);
        }
    }
}

// ---------------- GMF head: sigmoid((u*i)@W_out + b_out) ---------------------
__global__ void head_kernel(const int* __restrict__ uidx,
                            const int* __restrict__ iidx,
                            const float* __restrict__ Wout,
                            const float* __restrict__ bout,
                            float* __restrict__ out) {
    int gw = (blockIdx.x * blockDim.x + threadIdx.x) >> 5;
    if (gw >= BATCH_) return;
    int lane = threadIdx.x & 31;
    int u  = __ldg(&uidx[gw]);
    int it = __ldg(&iidx[gw]) + N_USER;
    const float4* ur = (const float4*)(g_all + (size_t)u  * 256);
    const float4* ir = (const float4*)(g_all + (size_t)it * 256);
    const float4* w4 = (const float4*)Wout;
    float acc = 0.f;
#pragma unroll
    for (int q = 0; q < 2; q++) {
        int c = lane + q * 32;
        float4 a = ur[c];
        float4 b = ir[c];
        float4 w = __ldg(&w4[c]);
        acc += a.x * b.x * w.x + a.y * b.y * w.y + a.z * b.z * w.z + a.w * b.w * w.w;
    }
#pragma unroll
    for (int off = 16; off; off >>= 1)
        acc += __shfl_xor_sync(0xffffffffu, acc, off);
    if (lane == 0) {
        float z = acc + __ldg(bout);
        out[gw] = 1.0f / (1.0f + expf(-z));
    }
}

// ---------------- launch ------------------------------------------------------
extern "C" void kernel_launch(void* const* d_in, const int* in_sizes, int n_in,
                              void* d_out, int out_size) {
    const int*   user_idx = (const int*)  d_in[0];
    const int*   item_idx = (const int*)  d_in[1];
    const int*   adj_rows = (const int*)  d_in[2];
    const int*   adj_cols = (const int*)  d_in[3];
    const float* adj_vals = (const float*)d_in[4];
    const float* user_emb = (const float*)d_in[5];
    const float* item_emb = (const float*)d_in[6];
    const float* W_gc     = (const float*)d_in[7];
    const float* b_gc     = (const float*)d_in[8];
    const float* W_bi     = (const float*)d_in[9];
    const float* b_bi     = (const float*)d_in[10];
    const float* W_out    = (const float*)d_in[11];
    const float* b_out    = (const float*)d_in[12];
    float* out = (float*)d_out;

    const int smem = (64 * TPAD * 2 + 64 * 64 * 2 + 64) * (int)sizeof(float); // 100608 B
    cudaFuncSetAttribute(transform_kernel,
                         cudaFuncAttributeMaxDynamicSharedMemorySize, smem);

    const int vec_blocks = (N_NODES_ * EMB / 4) / 256;   // 9375 exactly
    init_kernel<<<vec_blocks, 256>>>(user_emb, item_emb);

    const int spmm_blocks = (NNZ_ * 16) / 256;           // 300000 exactly
    const int tile_blocks = (N_NODES_ + 127) / 128;      // 1172

    for (int l = 0; l < N_LAYERS; l++) {
        spmm_kernel<<<spmm_blocks, 256>>>(adj_rows, adj_cols, adj_vals);
        transform_kernel<<<tile_blocks, 256, smem>>>(W_gc + l * EMB * EMB,
                                                     b_gc + l * EMB,
                                                     W_bi + l * EMB * EMB,
                                                     b_bi + l * EMB,
                                                     l);
    }

    head_kernel<<<(BATCH_ * 32) / 256, 256>>>(user_idx, item_idx, W_out, b_out, out);
}

// round 3
// speedup vs baseline: 1.6209x; 1.6209x over previous
#include <cuda_runtime.h>
#include <math.h>

#define N_USER   100000
#define N_ITEM   50000
#define N_NODES_ (N_USER + N_ITEM)   // 150000
#define NNZ_     4800000
#define EMB      64
#define N_LAYERS 3
#define BATCH_   16384
#define EPS_     1e-12f
#define NEG_SLOPE 0.2f
#define SPAD     68                   // row pad for S/P tiles (16B-aligned k-quads)

// ---------------- scratch (device globals: allocation-free rule) -------------
__device__ float g_ego [N_NODES_ * EMB];        // current layer input (unnormalized)
__device__ float g_side[N_NODES_ * EMB];        // A_hat @ ego accumulator
__device__ float g_all [N_NODES_ * 4 * EMB];    // concat of 4 embedding blocks

// ------- init: ego = concat(user_emb, item_emb); all[:,0:64] = ego; side = 0 --
__global__ void init_kernel(const float* __restrict__ ue, const float* __restrict__ ie) {
    int idx = blockIdx.x * blockDim.x + threadIdx.x;      // float4 index
    const int total = N_NODES_ * EMB / 4;
    if (idx >= total) return;
    int node = idx >> 4;
    int c4   = idx & 15;
    float4 v;
    if (node < N_USER) v = __ldg((const float4*)ue + node * 16 + c4);
    else               v = __ldg((const float4*)ie + (node - N_USER) * 16 + c4);
    ((float4*)g_ego)[idx] = v;
    ((float4*)g_all)[node * 64 + c4] = v;
    ((float4*)g_side)[idx] = make_float4(0.f, 0.f, 0.f, 0.f);
}

// ---------------- SpMM: side[r] += val * ego[c] -------------------------------
// 16 lanes per edge, 2 independent edges per thread (MLP=2 to hide L2 latency).
__global__ void spmm_kernel(const int* __restrict__ rows,
                            const int* __restrict__ cols,
                            const float* __restrict__ vals) {
    int t = blockIdx.x * blockDim.x + threadIdx.x;
    int pair = t >> 4;                  // edge pair id
    int l = t & 15;
    int e0 = pair * 2;
    int e1 = e0 + 1;
    if (e1 >= NNZ_) { if (e0 >= NNZ_) return; e1 = e0; }

    // broadcast index loads (same addr across 16 lanes -> 1 wavefront each)
    int   r0 = __ldg(&rows[e0]);
    int   r1 = __ldg(&rows[e1]);
    int   c0 = __ldg(&cols[e0]);
    int   c1 = __ldg(&cols[e1]);
    float v0 = __ldg(&vals[e0]);
    float v1 = __ldg(&vals[e1]);

    // two independent gathers in flight
    float4 g0 = __ldg((const float4*)g_ego + c0 * 16 + l);
    float4 g1 = __ldg((const float4*)g_ego + c1 * 16 + l);

    float4 m0 = make_float4(g0.x * v0, g0.y * v0, g0.z * v0, g0.w * v0);
    float4 m1 = make_float4(g1.x * v1, g1.y * v1, g1.z * v1, g1.w * v1);
    float* d0 = g_side + ((size_t)r0 * EMB + l * 4);
    float* d1 = g_side + ((size_t)r1 * EMB + l * 4);
    asm volatile("red.global.add.v4.f32 [%0], {%1,%2,%3,%4};"
                 :: "l"(d0), "f"(m0.x), "f"(m0.y), "f"(m0.z), "f"(m0.w) : "memory");
    if (e1 != e0)
        asm volatile("red.global.add.v4.f32 [%0], {%1,%2,%3,%4};"
                     :: "l"(d1), "f"(m1.x), "f"(m1.y), "f"(m1.z), "f"(m1.w) : "memory");
}

// ---------------- fused dense transform + leaky_relu + L2-normalize ----------
// 64-row tile, 256 threads, thread(tx,ty): rows ty*4..+3, cols tx*4..+3.
// Inner loop over k in quads: S/P rows loaded as float4 along k (wavefront-
// efficient), weights as float4 along cols. Fuses g_side zeroing (coalesced).
__global__ void transform_kernel(const float* __restrict__ Wgc,
                                 const float* __restrict__ bgc,
                                 const float* __restrict__ Wbi,
                                 const float* __restrict__ bbi,
                                 int layer) {
    extern __shared__ float sh[];
    float* Ssh = sh;                    // [64][SPAD]
    float* Psh = Ssh + 64 * SPAD;       // [64][SPAD]
    float* Wg  = Psh + 64 * SPAD;       // [64][64]
    float* Wb  = Wg  + 64 * 64;         // [64][64]
    float* bs  = Wb  + 64 * 64;         // [64]

    const int tid = threadIdx.x;
    const int rowBase = blockIdx.x * 64;

    // stage weights (1024 float4 each)
    for (int i = tid; i < 1024; i += 256) {
        ((float4*)Wg)[i] = __ldg((const float4*)Wgc + i);
        ((float4*)Wb)[i] = __ldg((const float4*)Wbi + i);
    }
    if (tid < 64) bs[tid] = __ldg(bgc + tid) + __ldg(bbi + tid);

    // stage S and P=ego*side, coalesced global access; fused zero of g_side
#pragma unroll
    for (int it = 0; it < 4; it++) {
        int i  = tid + 256 * it;        // 0..1023
        int r  = i >> 4;
        int c4 = i & 15;
        int gr = rowBase + r;
        float4 s = make_float4(0.f, 0.f, 0.f, 0.f);
        float4 e = make_float4(0.f, 0.f, 0.f, 0.f);
        if (gr < N_NODES_) {
            s = ((const float4*)g_side)[gr * 16 + c4];
            e = ((const float4*)g_ego )[gr * 16 + c4];
            ((float4*)g_side)[gr * 16 + c4] = make_float4(0.f, 0.f, 0.f, 0.f);
        }
        *(float4*)&Ssh[r * SPAD + c4 * 4] = s;
        *(float4*)&Psh[r * SPAD + c4 * 4] =
            make_float4(e.x * s.x, e.y * s.y, e.z * s.z, e.w * s.w);
    }
    __syncthreads();

    const int tx = tid & 15;
    const int ty = tid >> 4;
    const int row0 = ty * 4;
    const int colBase = tx * 4;

    float acc[4][4];
#pragma unroll
    for (int i = 0; i < 4; i++)
#pragma unroll
        for (int j = 0; j < 4; j++) acc[i][j] = 0.f;

#pragma unroll 2
    for (int kq = 0; kq < 16; kq++) {
        // S/P: 4 rows x 4 consecutive k values as float4 (one wavefront each)
        float sA[4][4], pA[4][4];
#pragma unroll
        for (int i = 0; i < 4; i++) {
            *(float4*)sA[i] = *(const float4*)&Ssh[(row0 + i) * SPAD + kq * 4];
            *(float4*)pA[i] = *(const float4*)&Psh[(row0 + i) * SPAD + kq * 4];
        }
#pragma unroll
        for (int j = 0; j < 4; j++) {
            int k = kq * 4 + j;
            float4 wg = *(const float4*)&Wg[k * 64 + colBase];
            float4 wb = *(const float4*)&Wb[k * 64 + colBase];
#pragma unroll
            for (int i = 0; i < 4; i++) {
                float s = sA[i][j], p = pA[i][j];
                acc[i][0] += s * wg.x + p * wb.x;
                acc[i][1] += s * wg.y + p * wb.y;
                acc[i][2] += s * wg.z + p * wb.z;
                acc[i][3] += s * wg.w + p * wb.w;
            }
        }
    }

    // epilogue: bias + leaky, row-norm across 16 tx lanes (stay in half-warp)
    float b0 = bs[colBase + 0], b1 = bs[colBase + 1];
    float b2 = bs[colBase + 2], b3 = bs[colBase + 3];
#pragma unroll
    for (int i = 0; i < 4; i++) {
        float x0 = acc[i][0] + b0;
        float x1 = acc[i][1] + b1;
        float x2 = acc[i][2] + b2;
        float x3 = acc[i][3] + b3;
        x0 = fmaxf(x0, NEG_SLOPE * x0);
        x1 = fmaxf(x1, NEG_SLOPE * x1);
        x2 = fmaxf(x2, NEG_SLOPE * x2);
        x3 = fmaxf(x3, NEG_SLOPE * x3);
        float sq = x0 * x0 + x1 * x1 + x2 * x2 + x3 * x3;
#pragma unroll
        for (int off = 1; off < 16; off <<= 1)
            sq += __shfl_xor_sync(0xffffffffu, sq, off);
        int gr = rowBase + row0 + i;
        if (gr < N_NODES_) {
            float inv = 1.0f / fmaxf(sqrtf(sq), EPS_);
            *(float4*)&g_ego[(size_t)gr * EMB + colBase] =
                make_float4(x0, x1, x2, x3);
            *(float4*)&g_all[(size_t)gr * 256 + (layer + 1) * 64 + colBase] =
                make_float4(x0 * inv, x1 * inv, x2 * inv, x3 * inv);
        }
    }
}

// ---------------- GMF head: sigmoid((u*i)@W_out + b_out) ---------------------
__global__ void head_kernel(const int* __restrict__ uidx,
                            const int* __restrict__ iidx,
                            const float* __restrict__ Wout,
                            const float* __restrict__ bout,
                            float* __restrict__ out) {
    int gw = (blockIdx.x * blockDim.x + threadIdx.x) >> 5;
    if (gw >= BATCH_) return;
    int lane = threadIdx.x & 31;
    int u  = __ldg(&uidx[gw]);
    int it = __ldg(&iidx[gw]) + N_USER;
    const float4* ur = (const float4*)(g_all + (size_t)u  * 256);
    const float4* ir = (const float4*)(g_all + (size_t)it * 256);
    const float4* w4 = (const float4*)Wout;
    float acc = 0.f;
#pragma unroll
    for (int q = 0; q < 2; q++) {
        int c = lane + q * 32;
        float4 a = ur[c];
        float4 b = ir[c];
        float4 w = __ldg(&w4[c]);
        acc += a.x * b.x * w.x + a.y * b.y * w.y + a.z * b.z * w.z + a.w * b.w * w.w;
    }
#pragma unroll
    for (int off = 16; off; off >>= 1)
        acc += __shfl_xor_sync(0xffffffffu, acc, off);
    if (lane == 0) {
        float z = acc + __ldg(bout);
        out[gw] = 1.0f / (1.0f + expf(-z));
    }
}

// ---------------- launch ------------------------------------------------------
extern "C" void kernel_launch(void* const* d_in, const int* in_sizes, int n_in,
                              void* d_out, int out_size) {
    const int*   user_idx = (const int*)  d_in[0];
    const int*   item_idx = (const int*)  d_in[1];
    const int*   adj_rows = (const int*)  d_in[2];
    const int*   adj_cols = (const int*)  d_in[3];
    const float* adj_vals = (const float*)d_in[4];
    const float* user_emb = (const float*)d_in[5];
    const float* item_emb = (const float*)d_in[6];
    const float* W_gc     = (const float*)d_in[7];
    const float* b_gc     = (const float*)d_in[8];
    const float* W_bi     = (const float*)d_in[9];
    const float* b_bi     = (const float*)d_in[10];
    const float* W_out    = (const float*)d_in[11];
    const float* b_out    = (const float*)d_in[12];
    float* out = (float*)d_out;

    const int smem = (64 * SPAD * 2 + 64 * 64 * 2 + 64) * (int)sizeof(float); // 67840 B
    cudaFuncSetAttribute(transform_kernel,
                         cudaFuncAttributeMaxDynamicSharedMemorySize, smem);

    const int vec_blocks = (N_NODES_ * EMB / 4) / 256;   // 9375 exactly
    init_kernel<<<vec_blocks, 256>>>(user_emb, item_emb);

    const int spmm_blocks = ((NNZ_ / 2) * 16) / 256;     // 150000 exactly
    const int tile_blocks = (N_NODES_ + 63) / 64;        // 2344

    for (int l = 0; l < N_LAYERS; l++) {
        spmm_kernel<<<spmm_blocks, 256>>>(adj_rows, adj_cols, adj_vals);
        transform_kernel<<<tile_blocks, 256, smem>>>(W_gc + l * EMB * EMB,
                                                     b_gc + l * EMB,
                                                     W_bi + l * EMB * EMB,
                                                     b_bi + l * EMB,
                                                     l);
    }

    head_kernel<<<(BATCH_ * 32) / 256, 256>>>(user_idx, item_idx, W_out, b_out, out);
}

// round 4
// speedup vs baseline: 1.6800x; 1.0365x over previous
#include <cuda_runtime.h>
#include <math.h>

#define N_USER   100000
#define N_ITEM   50000
#define N_NODES_ (N_USER + N_ITEM)   // 150000
#define NNZ_     4800000
#define EMB      64
#define N_LAYERS 3
#define BATCH_   16384
#define EPS_     1e-12f
#define NEG_SLOPE 0.2f

// ---------------- scratch (device globals: allocation-free rule) -------------
__device__ float g_ego [N_NODES_ * EMB];        // current layer input (unnormalized)
__device__ float g_side[N_NODES_ * EMB];        // A_hat @ ego accumulator
__device__ float g_all [N_NODES_ * 4 * EMB];    // concat of 4 embedding blocks

// ------- init: ego = concat(user_emb, item_emb); all[:,0:64] = ego; side = 0 --
__global__ void init_kernel(const float* __restrict__ ue, const float* __restrict__ ie) {
    int idx = blockIdx.x * blockDim.x + threadIdx.x;      // float4 index
    const int total = N_NODES_ * EMB / 4;
    if (idx >= total) return;
    int node = idx >> 4;
    int c4   = idx & 15;
    float4 v;
    if (node < N_USER) v = __ldg((const float4*)ue + node * 16 + c4);
    else               v = __ldg((const float4*)ie + (node - N_USER) * 16 + c4);
    ((float4*)g_ego)[idx] = v;
    ((float4*)g_all)[node * 64 + c4] = v;
    ((float4*)g_side)[idx] = make_float4(0.f, 0.f, 0.f, 0.f);
}

// ---------------- SpMM: side[r] += val * ego[c] -------------------------------
// 16 lanes per edge-quad: 4 independent edges per thread (MLP=4).
// Index metadata loaded as one int4/int4/float4 broadcast per stream.
// NNZ is an exact multiple of 4; grid covers all quads exactly.
__global__ void spmm_kernel(const int* __restrict__ rows,
                            const int* __restrict__ cols,
                            const float* __restrict__ vals) {
    int t = blockIdx.x * blockDim.x + threadIdx.x;
    int quad = t >> 4;                  // edge-quad id (4 consecutive edges)
    int l = t & 15;

    int4   r4 = __ldg((const int4*)  rows + quad);
    int4   c4 = __ldg((const int4*)  cols + quad);
    float4 v4 = __ldg((const float4*)vals + quad);

    // four independent gathers in flight
    float4 g0 = __ldg((const float4*)g_ego + c4.x * 16 + l);
    float4 g1 = __ldg((const float4*)g_ego + c4.y * 16 + l);
    float4 g2 = __ldg((const float4*)g_ego + c4.z * 16 + l);
    float4 g3 = __ldg((const float4*)g_ego + c4.w * 16 + l);

    float4 m0 = make_float4(g0.x * v4.x, g0.y * v4.x, g0.z * v4.x, g0.w * v4.x);
    float4 m1 = make_float4(g1.x * v4.y, g1.y * v4.y, g1.z * v4.y, g1.w * v4.y);
    float4 m2 = make_float4(g2.x * v4.z, g2.y * v4.z, g2.z * v4.z, g2.w * v4.z);
    float4 m3 = make_float4(g3.x * v4.w, g3.y * v4.w, g3.z * v4.w, g3.w * v4.w);

    float* d0 = g_side + ((size_t)r4.x * EMB + l * 4);
    float* d1 = g_side + ((size_t)r4.y * EMB + l * 4);
    float* d2 = g_side + ((size_t)r4.z * EMB + l * 4);
    float* d3 = g_side + ((size_t)r4.w * EMB + l * 4);
    asm volatile("red.global.add.v4.f32 [%0], {%1,%2,%3,%4};"
                 :: "l"(d0), "f"(m0.x), "f"(m0.y), "f"(m0.z), "f"(m0.w) : "memory");
    asm volatile("red.global.add.v4.f32 [%0], {%1,%2,%3,%4};"
                 :: "l"(d1), "f"(m1.x), "f"(m1.y), "f"(m1.z), "f"(m1.w) : "memory");
    asm volatile("red.global.add.v4.f32 [%0], {%1,%2,%3,%4};"
                 :: "l"(d2), "f"(m2.x), "f"(m2.y), "f"(m2.z), "f"(m2.w) : "memory");
    asm volatile("red.global.add.v4.f32 [%0], {%1,%2,%3,%4};"
                 :: "l"(d3), "f"(m3.x), "f"(m3.y), "f"(m3.z), "f"(m3.w) : "memory");
}

// ---------------- fused dense transform + leaky_relu + L2-normalize ----------
// EXACT R1 structure (measured 92us): 64-row tile, 256 threads,
// thread(ty,tx) computes rows ty*4..+3, cols tx*4..+3, scalar broadcast LDS
// for row operands, float4 LDS for weights. Adds fused g_side zeroing.
__global__ void transform_kernel(const float* __restrict__ Wgc,
                                 const float* __restrict__ bgc,
                                 const float* __restrict__ Wbi,
                                 const float* __restrict__ bbi,
                                 int layer) {
    extern __shared__ float sh[];
    float* Ssh = sh;                    // [64][65]
    float* Psh = Ssh + 64 * 65;         // [64][65]
    float* Wg  = Psh + 64 * 65;         // [64][64]
    float* Wb  = Wg  + 64 * 64;         // [64][64]
    float* bs  = Wb  + 64 * 64;         // [64]

    const int tid = threadIdx.x;
    const int rowBase = blockIdx.x * 64;

    // stage weights (4096 floats each = 1024 float4)
    for (int i = tid; i < 1024; i += 256) {
        ((float4*)Wg)[i] = __ldg((const float4*)Wgc + i);
        ((float4*)Wb)[i] = __ldg((const float4*)Wbi + i);
    }
    if (tid < 64) bs[tid] = __ldg(bgc + tid) + __ldg(bbi + tid);

    // stage side & ego*side tiles (64 rows x 16 float4), coalesced; fused zero
    for (int i = tid; i < 1024; i += 256) {
        int r  = i >> 4;
        int c4 = i & 15;
        int gr = rowBase + r;
        float4 s = make_float4(0.f, 0.f, 0.f, 0.f);
        float4 e = make_float4(0.f, 0.f, 0.f, 0.f);
        if (gr < N_NODES_) {
            s = ((const float4*)g_side)[gr * 16 + c4];
            e = ((const float4*)g_ego )[gr * 16 + c4];
            ((float4*)g_side)[gr * 16 + c4] = make_float4(0.f, 0.f, 0.f, 0.f);
        }
        float* sp = Ssh + r * 65 + c4 * 4;
        sp[0] = s.x; sp[1] = s.y; sp[2] = s.z; sp[3] = s.w;
        float* pp = Psh + r * 65 + c4 * 4;
        pp[0] = e.x * s.x; pp[1] = e.y * s.y; pp[2] = e.z * s.z; pp[3] = e.w * s.w;
    }
    __syncthreads();

    const int tx = tid & 15;
    const int ty = tid >> 4;
    float acc[4][4];
#pragma unroll
    for (int i = 0; i < 4; i++)
#pragma unroll
        for (int j = 0; j < 4; j++) acc[i][j] = 0.f;

#pragma unroll 8
    for (int k = 0; k < 64; k++) {
        float4 bg = *(const float4*)&Wg[k * 64 + tx * 4];
        float4 bb = *(const float4*)&Wb[k * 64 + tx * 4];
        float as[4], ap[4];
#pragma unroll
        for (int i = 0; i < 4; i++) {
            as[i] = Ssh[(ty * 4 + i) * 65 + k];   // broadcast across tx lanes
            ap[i] = Psh[(ty * 4 + i) * 65 + k];
        }
#pragma unroll
        for (int i = 0; i < 4; i++) {
            acc[i][0] += as[i] * bg.x + ap[i] * bb.x;
            acc[i][1] += as[i] * bg.y + ap[i] * bb.y;
            acc[i][2] += as[i] * bg.z + ap[i] * bb.z;
            acc[i][3] += as[i] * bg.w + ap[i] * bb.w;
        }
    }

    // epilogue: bias + leaky, row-norm reduction across 16 tx lanes
    const int colBase = tx * 4;
    float v[4][4];
    float sq[4];
#pragma unroll
    for (int i = 0; i < 4; i++) {
        float x0 = acc[i][0] + bs[colBase + 0];
        float x1 = acc[i][1] + bs[colBase + 1];
        float x2 = acc[i][2] + bs[colBase + 2];
        float x3 = acc[i][3] + bs[colBase + 3];
        x0 = fmaxf(x0, NEG_SLOPE * x0);
        x1 = fmaxf(x1, NEG_SLOPE * x1);
        x2 = fmaxf(x2, NEG_SLOPE * x2);
        x3 = fmaxf(x3, NEG_SLOPE * x3);
        v[i][0] = x0; v[i][1] = x1; v[i][2] = x2; v[i][3] = x3;
        float s = x0 * x0 + x1 * x1 + x2 * x2 + x3 * x3;
#pragma unroll
        for (int off = 1; off < 16; off <<= 1)
            s += __shfl_xor_sync(0xffffffffu, s, off);
        sq[i] = s;
    }

#pragma unroll
    for (int i = 0; i < 4; i++) {
        int gr = rowBase + ty * 4 + i;
        if (gr >= N_NODES_) continue;
        float inv = 1.0f / fmaxf(sqrtf(sq[i]), EPS_);
        float4 raw = make_float4(v[i][0], v[i][1], v[i][2], v[i][3]);
        float4 nrm = make_float4(v[i][0] * inv, v[i][1] * inv, v[i][2] * inv, v[i][3] * inv);
        *(float4*)&g_ego[(size_t)gr * EMB + colBase] = raw;
        *(float4*)&g_all[(size_t)gr * 256 + (layer + 1) * 64 + colBase] = nrm;
    }
}

// ---------------- GMF head: sigmoid((u*i)@W_out + b_out) ---------------------
__global__ void head_kernel(const int* __restrict__ uidx,
                            const int* __restrict__ iidx,
                            const float* __restrict__ Wout,
                            const float* __restrict__ bout,
                            float* __restrict__ out) {
    int gw = (blockIdx.x * blockDim.x + threadIdx.x) >> 5;
    if (gw >= BATCH_) return;
    int lane = threadIdx.x & 31;
    int u  = __ldg(&uidx[gw]);
    int it = __ldg(&iidx[gw]) + N_USER;
    const float4* ur = (const float4*)(g_all + (size_t)u  * 256);
    const float4* ir = (const float4*)(g_all + (size_t)it * 256);
    const float4* w4 = (const float4*)Wout;
    float acc = 0.f;
#pragma unroll
    for (int q = 0; q < 2; q++) {
        int c = lane + q * 32;
        float4 a = ur[c];
        float4 b = ir[c];
        float4 w = __ldg(&w4[c]);
        acc += a.x * b.x * w.x + a.y * b.y * w.y + a.z * b.z * w.z + a.w * b.w * w.w;
    }
#pragma unroll
    for (int off = 16; off; off >>= 1)
        acc += __shfl_xor_sync(0xffffffffu, acc, off);
    if (lane == 0) {
        float z = acc + __ldg(bout);
        out[gw] = 1.0f / (1.0f + expf(-z));
    }
}

// ---------------- launch ------------------------------------------------------
extern "C" void kernel_launch(void* const* d_in, const int* in_sizes, int n_in,
                              void* d_out, int out_size) {
    const int*   user_idx = (const int*)  d_in[0];
    const int*   item_idx = (const int*)  d_in[1];
    const int*   adj_rows = (const int*)  d_in[2];
    const int*   adj_cols = (const int*)  d_in[3];
    const float* adj_vals = (const float*)d_in[4];
    const float* user_emb = (const float*)d_in[5];
    const float* item_emb = (const float*)d_in[6];
    const float* W_gc     = (const float*)d_in[7];
    const float* b_gc     = (const float*)d_in[8];
    const float* W_bi     = (const float*)d_in[9];
    const float* b_bi     = (const float*)d_in[10];
    const float* W_out    = (const float*)d_in[11];
    const float* b_out    = (const float*)d_in[12];
    float* out = (float*)d_out;

    const int smem = (64 * 65 * 2 + 64 * 64 * 2 + 64) * (int)sizeof(float);  // 66304 B
    cudaFuncSetAttribute(transform_kernel,
                         cudaFuncAttributeMaxDynamicSharedMemorySize, smem);

    const int vec_blocks = (N_NODES_ * EMB / 4) / 256;   // 9375 exactly
    init_kernel<<<vec_blocks, 256>>>(user_emb, item_emb);

    const int spmm_blocks = ((NNZ_ / 4) * 16) / 256;     // 75000 exactly
    const int tile_blocks = (N_NODES_ + 63) / 64;        // 2344

    for (int l = 0; l < N_LAYERS; l++) {
        spmm_kernel<<<spmm_blocks, 256>>>(adj_rows, adj_cols, adj_vals);
        transform_kernel<<<tile_blocks, 256, smem>>>(W_gc + l * EMB * EMB,
                                                     b_gc + l * EMB,
                                                     W_bi + l * EMB * EMB,
                                                     b_bi + l * EMB,
                                                     l);
    }

    head_kernel<<<(BATCH_ * 32) / 256, 256>>>(user_idx, item_idx, W_out, b_out, out);
}

// round 5
// speedup vs baseline: 2.4256x; 1.4438x over previous
#include <cuda_runtime.h>
#include <math.h>

#define N_USER   100000
#define N_ITEM   50000
#define N_NODES_ (N_USER + N_ITEM)   // 150000
#define NNZ_     4800000
#define EMB      64
#define N_LAYERS 3
#define BATCH_   16384
#define EPS_     1e-12f
#define NEG_SLOPE 0.2f

// ---------------- scratch (device globals: allocation-free rule) -------------
__device__ float g_ego [N_NODES_ * EMB];        // current layer input (unnormalized)
__device__ float g_side[N_NODES_ * EMB];        // A_hat @ ego (written whole by CSR spmm)
__device__ float g_all [N_NODES_ * 4 * EMB];    // concat of 4 embedding blocks
// CSR build scratch
__device__ int   g_row_cnt[N_NODES_];
__device__ int   g_row_cur[N_NODES_];
__device__ int   g_row_off[N_NODES_ + 1];
__device__ int   g_col_s  [NNZ_];
__device__ float g_val_s  [NNZ_];

// ------- init: ego = concat(user_emb, item_emb); all[:,0:64] = ego; counters=0
__global__ void init_kernel(const float* __restrict__ ue, const float* __restrict__ ie) {
    int idx = blockIdx.x * blockDim.x + threadIdx.x;      // float4 index
    const int total = N_NODES_ * EMB / 4;
    if (idx >= total) return;
    int node = idx >> 4;
    int c4   = idx & 15;
    float4 v;
    if (node < N_USER) v = __ldg((const float4*)ue + node * 16 + c4);
    else               v = __ldg((const float4*)ie + (node - N_USER) * 16 + c4);
    ((float4*)g_ego)[idx] = v;
    ((float4*)g_all)[node * 64 + c4] = v;
    if (idx < N_NODES_) { g_row_cnt[idx] = 0; g_row_cur[idx] = 0; }
}

// ---------------- CSR build: degree count ------------------------------------
__global__ void count_kernel(const int* __restrict__ rows) {
    int q = blockIdx.x * blockDim.x + threadIdx.x;
    if (q >= NNZ_ / 4) return;
    int4 r4 = __ldg((const int4*)rows + q);
    atomicAdd(&g_row_cnt[r4.x], 1);
    atomicAdd(&g_row_cnt[r4.y], 1);
    atomicAdd(&g_row_cnt[r4.z], 1);
    atomicAdd(&g_row_cnt[r4.w], 1);
}

// ---------------- CSR build: exclusive scan (single block, 1024 threads) -----
__global__ void scan_kernel() {
    __shared__ int part[1024];
    const int CH = (N_NODES_ + 1023) / 1024;   // 147
    int t = threadIdx.x;
    int base = t * CH;
    int s = 0;
    for (int i = 0; i < CH; i++) {
        int idx = base + i;
        if (idx < N_NODES_) s += g_row_cnt[idx];
    }
    part[t] = s;
    __syncthreads();
    // inclusive Kogge-Stone scan over 1024 partials
    for (int off = 1; off < 1024; off <<= 1) {
        int u = (t >= off) ? part[t - off] : 0;
        __syncthreads();
        part[t] += u;
        __syncthreads();
    }
    int run = part[t] - s;          // exclusive prefix for this chunk
    for (int i = 0; i < CH; i++) {
        int idx = base + i;
        if (idx < N_NODES_) {
            g_row_off[idx] = run;
            run += g_row_cnt[idx];
        }
    }
    if (t == 1023) g_row_off[N_NODES_] = part[1023];   // total = NNZ
}

// ---------------- CSR build: scatter edges into row-sorted arrays ------------
__global__ void scatter_kernel(const int* __restrict__ rows,
                               const int* __restrict__ cols,
                               const float* __restrict__ vals) {
    int q = blockIdx.x * blockDim.x + threadIdx.x;
    if (q >= NNZ_ / 4) return;
    int4   r4 = __ldg((const int4*)  rows + q);
    int4   c4 = __ldg((const int4*)  cols + q);
    float4 v4 = __ldg((const float4*)vals + q);
    int p;
    p = __ldg(&g_row_off[r4.x]) + atomicAdd(&g_row_cur[r4.x], 1);
    g_col_s[p] = c4.x; g_val_s[p] = v4.x;
    p = __ldg(&g_row_off[r4.y]) + atomicAdd(&g_row_cur[r4.y], 1);
    g_col_s[p] = c4.y; g_val_s[p] = v4.y;
    p = __ldg(&g_row_off[r4.z]) + atomicAdd(&g_row_cur[r4.z], 1);
    g_col_s[p] = c4.z; g_val_s[p] = v4.z;
    p = __ldg(&g_row_off[r4.w]) + atomicAdd(&g_row_cur[r4.w], 1);
    g_col_s[p] = c4.w; g_val_s[p] = v4.w;
}

// ---------------- CSR SpMM: side[r] = sum val*ego[c], no atomics, no zeroing --
// 16 lanes per row; register float4 accumulator; 4-edge unroll for MLP.
__global__ void spmm_csr_kernel() {
    int t = blockIdx.x * blockDim.x + threadIdx.x;
    int r = t >> 4;                 // row id (grid sized exactly)
    int l = t & 15;
    int beg = __ldg(&g_row_off[r]);
    int end = __ldg(&g_row_off[r + 1]);
    float4 acc = make_float4(0.f, 0.f, 0.f, 0.f);
    int e = beg;
    for (; e + 4 <= end; e += 4) {
        int   c0 = __ldg(&g_col_s[e + 0]);
        int   c1 = __ldg(&g_col_s[e + 1]);
        int   c2 = __ldg(&g_col_s[e + 2]);
        int   c3 = __ldg(&g_col_s[e + 3]);
        float v0 = __ldg(&g_val_s[e + 0]);
        float v1 = __ldg(&g_val_s[e + 1]);
        float v2 = __ldg(&g_val_s[e + 2]);
        float v3 = __ldg(&g_val_s[e + 3]);
        float4 g0 = __ldg((const float4*)g_ego + c0 * 16 + l);
        float4 g1 = __ldg((const float4*)g_ego + c1 * 16 + l);
        float4 g2 = __ldg((const float4*)g_ego + c2 * 16 + l);
        float4 g3 = __ldg((const float4*)g_ego + c3 * 16 + l);
        acc.x += g0.x * v0 + g1.x * v1 + g2.x * v2 + g3.x * v3;
        acc.y += g0.y * v0 + g1.y * v1 + g2.y * v2 + g3.y * v3;
        acc.z += g0.z * v0 + g1.z * v1 + g2.z * v2 + g3.z * v3;
        acc.w += g0.w * v0 + g1.w * v1 + g2.w * v2 + g3.w * v3;
    }
    for (; e < end; e++) {
        int   c = __ldg(&g_col_s[e]);
        float v = __ldg(&g_val_s[e]);
        float4 g = __ldg((const float4*)g_ego + c * 16 + l);
        acc.x += g.x * v; acc.y += g.y * v; acc.z += g.z * v; acc.w += g.w * v;
    }
    ((float4*)g_side)[r * 16 + l] = acc;
}

// ---------------- fused dense transform + leaky_relu + L2-normalize ----------
// R1-measured structure (92us): 64-row tile, 256 threads, thread(ty,tx)
// computes rows ty*4..+3, cols tx*4..+3. No g_side zeroing needed (CSR writes).
__global__ void transform_kernel(const float* __restrict__ Wgc,
                                 const float* __restrict__ bgc,
                                 const float* __restrict__ Wbi,
                                 const float* __restrict__ bbi,
                                 int layer) {
    extern __shared__ float sh[];
    float* Ssh = sh;                    // [64][65]
    float* Psh = Ssh + 64 * 65;         // [64][65]
    float* Wg  = Psh + 64 * 65;         // [64][64]
    float* Wb  = Wg  + 64 * 64;         // [64][64]
    float* bs  = Wb  + 64 * 64;         // [64]

    const int tid = threadIdx.x;
    const int rowBase = blockIdx.x * 64;

    for (int i = tid; i < 1024; i += 256) {
        ((float4*)Wg)[i] = __ldg((const float4*)Wgc + i);
        ((float4*)Wb)[i] = __ldg((const float4*)Wbi + i);
    }
    if (tid < 64) bs[tid] = __ldg(bgc + tid) + __ldg(bbi + tid);

    for (int i = tid; i < 1024; i += 256) {
        int r  = i >> 4;
        int c4 = i & 15;
        int gr = rowBase + r;
        float4 s = make_float4(0.f, 0.f, 0.f, 0.f);
        float4 e = make_float4(0.f, 0.f, 0.f, 0.f);
        if (gr < N_NODES_) {
            s = ((const float4*)g_side)[gr * 16 + c4];
            e = ((const float4*)g_ego )[gr * 16 + c4];
        }
        float* sp = Ssh + r * 65 + c4 * 4;
        sp[0] = s.x; sp[1] = s.y; sp[2] = s.z; sp[3] = s.w;
        float* pp = Psh + r * 65 + c4 * 4;
        pp[0] = e.x * s.x; pp[1] = e.y * s.y; pp[2] = e.z * s.z; pp[3] = e.w * s.w;
    }
    __syncthreads();

    const int tx = tid & 15;
    const int ty = tid >> 4;
    float acc[4][4];
#pragma unroll
    for (int i = 0; i < 4; i++)
#pragma unroll
        for (int j = 0; j < 4; j++) acc[i][j] = 0.f;

#pragma unroll 8
    for (int k = 0; k < 64; k++) {
        float4 bg = *(const float4*)&Wg[k * 64 + tx * 4];
        float4 bb = *(const float4*)&Wb[k * 64 + tx * 4];
        float as[4], ap[4];
#pragma unroll
        for (int i = 0; i < 4; i++) {
            as[i] = Ssh[(ty * 4 + i) * 65 + k];
            ap[i] = Psh[(ty * 4 + i) * 65 + k];
        }
#pragma unroll
        for (int i = 0; i < 4; i++) {
            acc[i][0] += as[i] * bg.x + ap[i] * bb.x;
            acc[i][1] += as[i] * bg.y + ap[i] * bb.y;
            acc[i][2] += as[i] * bg.z + ap[i] * bb.z;
            acc[i][3] += as[i] * bg.w + ap[i] * bb.w;
        }
    }

    const int colBase = tx * 4;
    float v[4][4];
    float sq[4];
#pragma unroll
    for (int i = 0; i < 4; i++) {
        float x0 = acc[i][0] + bs[colBase + 0];
        float x1 = acc[i][1] + bs[colBase + 1];
        float x2 = acc[i][2] + bs[colBase + 2];
        float x3 = acc[i][3] + bs[colBase + 3];
        x0 = fmaxf(x0, NEG_SLOPE * x0);
        x1 = fmaxf(x1, NEG_SLOPE * x1);
        x2 = fmaxf(x2, NEG_SLOPE * x2);
        x3 = fmaxf(x3, NEG_SLOPE * x3);
        v[i][0] = x0; v[i][1] = x1; v[i][2] = x2; v[i][3] = x3;
        float s = x0 * x0 + x1 * x1 + x2 * x2 + x3 * x3;
#pragma unroll
        for (int off = 1; off < 16; off <<= 1)
            s += __shfl_xor_sync(0xffffffffu, s, off);
        sq[i] = s;
    }

#pragma unroll
    for (int i = 0; i < 4; i++) {
        int gr = rowBase + ty * 4 + i;
        if (gr >= N_NODES_) continue;
        float inv = 1.0f / fmaxf(sqrtf(sq[i]), EPS_);
        float4 raw = make_float4(v[i][0], v[i][1], v[i][2], v[i][3]);
        float4 nrm = make_float4(v[i][0] * inv, v[i][1] * inv, v[i][2] * inv, v[i][3] * inv);
        *(float4*)&g_ego[(size_t)gr * EMB + colBase] = raw;
        *(float4*)&g_all[(size_t)gr * 256 + (layer + 1) * 64 + colBase] = nrm;
    }
}

// ---------------- GMF head: sigmoid((u*i)@W_out + b_out) ---------------------
__global__ void head_kernel(const int* __restrict__ uidx,
                            const int* __restrict__ iidx,
                            const float* __restrict__ Wout,
                            const float* __restrict__ bout,
                            float* __restrict__ out) {
    int gw = (blockIdx.x * blockDim.x + threadIdx.x) >> 5;
    if (gw >= BATCH_) return;
    int lane = threadIdx.x & 31;
    int u  = __ldg(&uidx[gw]);
    int it = __ldg(&iidx[gw]) + N_USER;
    const float4* ur = (const float4*)(g_all + (size_t)u  * 256);
    const float4* ir = (const float4*)(g_all + (size_t)it * 256);
    const float4* w4 = (const float4*)Wout;
    float acc = 0.f;
#pragma unroll
    for (int q = 0; q < 2; q++) {
        int c = lane + q * 32;
        float4 a = ur[c];
        float4 b = ir[c];
        float4 w = __ldg(&w4[c]);
        acc += a.x * b.x * w.x + a.y * b.y * w.y + a.z * b.z * w.z + a.w * b.w * w.w;
    }
#pragma unroll
    for (int off = 16; off; off >>= 1)
        acc += __shfl_xor_sync(0xffffffffu, acc, off);
    if (lane == 0) {
        float z = acc + __ldg(bout);
        out[gw] = 1.0f / (1.0f + expf(-z));
    }
}

// ---------------- launch ------------------------------------------------------
extern "C" void kernel_launch(void* const* d_in, const int* in_sizes, int n_in,
                              void* d_out, int out_size) {
    const int*   user_idx = (const int*)  d_in[0];
    const int*   item_idx = (const int*)  d_in[1];
    const int*   adj_rows = (const int*)  d_in[2];
    const int*   adj_cols = (const int*)  d_in[3];
    const float* adj_vals = (const float*)d_in[4];
    const float* user_emb = (const float*)d_in[5];
    const float* item_emb = (const float*)d_in[6];
    const float* W_gc     = (const float*)d_in[7];
    const float* b_gc     = (const float*)d_in[8];
    const float* W_bi     = (const float*)d_in[9];
    const float* b_bi     = (const float*)d_in[10];
    const float* W_out    = (const float*)d_in[11];
    const float* b_out    = (const float*)d_in[12];
    float* out = (float*)d_out;

    const int smem = (64 * 65 * 2 + 64 * 64 * 2 + 64) * (int)sizeof(float);  // 66304 B
    cudaFuncSetAttribute(transform_kernel,
                         cudaFuncAttributeMaxDynamicSharedMemorySize, smem);

    const int vec_blocks = (N_NODES_ * EMB / 4) / 256;   // 9375 exactly
    init_kernel<<<vec_blocks, 256>>>(user_emb, item_emb);

    const int q_blocks = (NNZ_ / 4 + 255) / 256;         // 4688
    count_kernel<<<q_blocks, 256>>>(adj_rows);
    scan_kernel<<<1, 1024>>>();
    scatter_kernel<<<q_blocks, 256>>>(adj_rows, adj_cols, adj_vals);

    const int spmm_blocks = (N_NODES_ * 16) / 256;       // 9375 exactly
    const int tile_blocks = (N_NODES_ + 63) / 64;        // 2344

    for (int l = 0; l < N_LAYERS; l++) {
        spmm_csr_kernel<<<spmm_blocks, 256>>>();
        transform_kernel<<<tile_blocks, 256, smem>>>(W_gc + l * EMB * EMB,
                                                     b_gc + l * EMB,
                                                     W_bi + l * EMB * EMB,
                                                     b_bi + l * EMB,
                                                     l);
    }

    head_kernel<<<(BATCH_ * 32) / 256, 256>>>(user_idx, item_idx, W_out, b_out, out);
}